// round 14
// baseline (speedup 1.0000x reference)
#include <cuda_runtime.h>
#include <math.h>

#define B_  128
#define T_  2048
#define D_  512
#define SPL 16                       // t-splits per batch
#define TS  (T_ / SPL)               // 128
#define NBG 16                       // batch groups of 8
#define M1_KS 8                      // m1 GEMM split-K (K=1024, 128-wide)
#define F2_KS 8                      // m1@W_m2 split-K (K=512, 64-wide)
#define FS_KS 16                     // msa@W_s split-K (K=512, 32-wide)

// block-role layout: tiles (first 256 also run m1 as prefix) | F2 | FS | epi
#define BID_TILE   0                         // [0, 2048); bid<256 do m1 first
#define BID_F2     (BID_TILE + B_ * SPL)     // [2048, 2304)
#define BID_FS     (BID_F2 + 256)            // [2304, 3328)  (1024 FS blocks)
#define BID_EPI    (BID_FS + 1024)           // [3328, 3456)
#define GRID_TOTAL (BID_EPI + B_)

// ---------------- scratch ----------------
__device__ float  g_part[B_ * SPL * D_];     // unnormalized msa partials (4 MB)
__device__ float2 g_stats[B_ * SPL];         // per-tile {local_max, local_expsum}
__device__ float  g_m1p[M1_KS][B_ * D_];     // m1 split-K partials
__device__ float  g_f2p[F2_KS][B_ * D_];     // m1@W_m2 partials
__device__ float  g_fsp[FS_KS][B_ * D_];     // msa@W_s partials

// pipeline counters (zero at load; reset by last epilogue block each run)
__device__ int c_m1;
__device__ int c_tile_bg[NBG];
__device__ int c_f2_bg[NBG];
__device__ int c_fs_bg[NBG];
__device__ int c_epi;

__device__ __forceinline__ void block_signal(int* c) {
    __threadfence();
    __syncthreads();
    if (threadIdx.x == 0) atomicAdd(c, 1);
}
__device__ __forceinline__ void block_wait(int* c, int target) {
    if (threadIdx.x == 0) {
        while (atomicAdd(c, 0) < target) __nanosleep(128);
        __threadfence();
    }
    __syncthreads();
}

__global__ __launch_bounds__(256, 5) void kmain(const float* __restrict__ past,
                                                const float* __restrict__ control,
                                                const float* __restrict__ W_ca,
                                                const float* __restrict__ b_ca,
                                                const float* __restrict__ memory,
                                                const float* __restrict__ read,
                                                const float* __restrict__ W_m1,
                                                const float* __restrict__ b_m1,
                                                const float* __restrict__ W_m2,
                                                const float* __restrict__ b_m2,
                                                const float* __restrict__ W_s,
                                                const float* __restrict__ b_s,
                                                const float* __restrict__ W_m3,
                                                const float* __restrict__ b_m3,
                                                float* __restrict__ out)
{
    __shared__ __align__(16) float sbuf[8 * 128 + 8 * 16];   // 4.5 KB, carved per role
    const int tid = threadIdx.x;
    const int bid = blockIdx.x;

    // ================= tiles (+ m1 GEMM prefix for bid < 256) =================
    if (bid < BID_F2) {
        if (bid < 256) {
            // ---- m1 GEMM prefix (split-K 8, 128-wide) ----
            const int ks = bid & 7, bg = (bid >> 3) & 15, st = bid >> 7;
            const int k = st * 256 + tid;
            float (*s_a)[128] = reinterpret_cast<float (*)[128]>(sbuf);
            for (int i = tid; i < 8 * 128; i += 256) {
                const int bb = i >> 7, j = i & 127;
                const int jj = ks * 128 + j;
                const int b = bg * 8 + bb;
                s_a[bb][j] = (jj < D_) ? memory[b * D_ + jj] : read[b * D_ + (jj - D_)];
            }
            __syncthreads();
            float acc[8] = {};
            const float* Wb = W_m1 + (size_t)(ks * 128) * D_ + k;
            #pragma unroll 4
            for (int j = 0; j < 128; j++) {
                const float wv = __ldg(&Wb[(size_t)j * D_]);
                #pragma unroll
                for (int bb = 0; bb < 8; bb++) acc[bb] += s_a[bb][j] * wv;
            }
            #pragma unroll
            for (int bb = 0; bb < 8; bb++)
                g_m1p[ks][(size_t)(bg * 8 + bb) * D_ + k] = acc[bb];
            block_signal(&c_m1);   // includes __syncthreads; sbuf safe to reuse
        }

        // ---- fused logits+msa tile ----
        // carve: [0,512) c*W_ca (float4[128]); [512,640) logits; [640,768) weights; [768] red
        float4* s_cw    = reinterpret_cast<float4*>(sbuf);
        float*  s_logit = sbuf + 512;
        float*  s_w     = sbuf + 640;
        float*  s_red   = sbuf + 768;

        const int idx = bid - BID_TILE;
        const int b = idx >> 4, s = idx & 15;
        const int warp = tid >> 5, lane = tid & 31;
        const float* cbase = past + (size_t)b * T_ * (2 * D_) + (size_t)s * TS * (2 * D_);

        if (tid < D_ / 4) {
            float4 c = reinterpret_cast<const float4*>(control + (size_t)b * D_)[tid];
            float4 w = reinterpret_cast<const float4*>(W_ca)[tid];
            s_cw[tid] = make_float4(c.x * w.x, c.y * w.y, c.z * w.z, c.w * w.w);
        }
        __syncthreads();

        // --- phase A: 128 logits (8 warps x 16 t, two groups of 8 for MLP) ---
        const float bias = b_ca[0];
        #pragma unroll
        for (int g = 0; g < 2; g++) {
            const int t0 = warp * 16 + g * 8;
            float acc[8] = {};
            #pragma unroll
            for (int j = 0; j < 4; j++) {
                const float4 c = s_cw[lane + j * 32];
                #pragma unroll
                for (int i = 0; i < 8; i++) {
                    float4 v = __ldcs(reinterpret_cast<const float4*>(
                                   cbase + (size_t)(t0 + i) * (2 * D_)) + lane + j * 32);
                    acc[i] += v.x * c.x + v.y * c.y + v.z * c.z + v.w * c.w;
                }
            }
            #pragma unroll
            for (int i = 0; i < 8; i++) {
                float a = acc[i];
                #pragma unroll
                for (int o = 16; o; o >>= 1) a += __shfl_xor_sync(0xffffffffu, a, o);
                if (lane == 0) s_logit[t0 + i] = a + bias;
            }
        }
        __syncthreads();

        // --- local softmax stats (warp 0) ---
        if (warp == 0) {
            float v[4], m = -3.4e38f;
            #pragma unroll
            for (int q = 0; q < 4; q++) {
                float x = s_logit[lane + q * 32];
                if (x == 0.f) x = -1e9f;              // padding mask
                v[q] = x;
                m = fmaxf(m, x);
            }
            #pragma unroll
            for (int o = 16; o; o >>= 1) m = fmaxf(m, __shfl_xor_sync(0xffffffffu, m, o));
            float sum = 0.f;
            #pragma unroll
            for (int q = 0; q < 4; q++) sum += expf(v[q] - m);
            #pragma unroll
            for (int o = 16; o; o >>= 1) sum += __shfl_xor_sync(0xffffffffu, sum, o);
            if (lane == 0) { s_red[0] = m; g_stats[b * SPL + s] = make_float2(m, sum); }
        }
        __syncthreads();
        const float mx = s_red[0];
        if (tid < TS) {
            float x = s_logit[tid];
            if (x == 0.f) x = -1e9f;
            s_w[tid] = expf(x - mx);                  // unnormalized weight
        }
        __syncthreads();

        // --- phase B: weighted sum of memories half (float4; two row-parity halves) ---
        const float4* rbase = reinterpret_cast<const float4*>(cbase);   // row stride 256 float4
        const int c = tid & 127, half = tid >> 7;
        float4 a0 = {0,0,0,0}, a1 = {0,0,0,0};
        #pragma unroll 8
        for (int t = half; t < TS; t += 8) {
            float4 v0 = __ldcs(&rbase[(size_t)(t    ) * 256 + 128 + c]);
            float4 v1 = __ldcs(&rbase[(size_t)(t + 2) * 256 + 128 + c]);
            float4 v2 = __ldcs(&rbase[(size_t)(t + 4) * 256 + 128 + c]);
            float4 v3 = __ldcs(&rbase[(size_t)(t + 6) * 256 + 128 + c]);
            const float w0 = s_w[t], w1 = s_w[t + 2], w2 = s_w[t + 4], w3 = s_w[t + 6];
            a0.x += w0 * v0.x; a0.y += w0 * v0.y; a0.z += w0 * v0.z; a0.w += w0 * v0.w;
            a1.x += w1 * v1.x; a1.y += w1 * v1.y; a1.z += w1 * v1.z; a1.w += w1 * v1.w;
            a0.x += w2 * v2.x; a0.y += w2 * v2.y; a0.z += w2 * v2.z; a0.w += w2 * v2.w;
            a1.x += w3 * v3.x; a1.y += w3 * v3.y; a1.z += w3 * v3.z; a1.w += w3 * v3.w;
        }
        float4 acc = make_float4(a0.x + a1.x, a0.y + a1.y, a0.z + a1.z, a0.w + a1.w);

        // cross-half combine (reuse s_cw region; phase A no longer needs it)
        __syncthreads();
        if (half == 1) s_cw[c] = acc;
        __syncthreads();
        if (half == 0) {
            float4 o = s_cw[c];
            o.x += acc.x; o.y += acc.y; o.z += acc.z; o.w += acc.w;
            reinterpret_cast<float4*>(g_part + (size_t)(b * SPL + s) * D_)[c] = o;
        }
        block_signal(&c_tile_bg[b >> 3]);
        return;
    }

    // ================= m1@W_m2 GEMM (split-K 8, 64-wide); waits on m1 =================
    if (bid < BID_FS) {
        block_wait(&c_m1, 256);
        const int idx = bid - BID_F2;
        const int ks = idx & 7, bg = (idx >> 3) & 15, st = idx >> 7;
        const int k = st * 256 + tid;
        float (*s_m1)[64] = reinterpret_cast<float (*)[64]>(sbuf);
        for (int i = tid; i < 8 * 64; i += 256) {
            const int bb = i >> 6, j = i & 63;
            const int jj = ks * 64 + j;
            const int b = bg * 8 + bb;
            float m1 = b_m1[jj];
            #pragma unroll
            for (int p = 0; p < M1_KS; p++) m1 += g_m1p[p][(size_t)b * D_ + jj];
            s_m1[bb][j] = m1;
        }
        __syncthreads();
        float acc[8] = {};
        const float* Wb = W_m2 + (size_t)(ks * 64) * D_ + k;
        #pragma unroll 4
        for (int j = 0; j < 64; j++) {
            const float wv = __ldg(&Wb[(size_t)j * D_]);
            #pragma unroll
            for (int bb = 0; bb < 8; bb++) acc[bb] += s_m1[bb][j] * wv;
        }
        #pragma unroll
        for (int bb = 0; bb < 8; bb++)
            g_f2p[ks][(size_t)(bg * 8 + bb) * D_ + k] = acc[bb];
        block_signal(&c_f2_bg[bg]);
        return;
    }

    // ================= msa@W_s GEMM (split-K 16, 32-wide, 4 batches/block) =================
    if (bid < BID_EPI) {
        const int idx = bid - BID_FS;            // [0, 1024)
        const int ks = idx & 15;                 // 16 k-slices (32-wide)
        const int bh = (idx >> 4) & 1;           // batch half within bg (4 batches)
        const int bg = (idx >> 5) & 15;
        const int st = idx >> 9;                 // 2 column tiles of 256
        block_wait(&c_tile_bg[bg], 8 * SPL);
        const int k = st * 256 + tid;
        const int b0 = bg * 8 + bh * 4;

        float (*s_msa)[32]   = reinterpret_cast<float (*)[32]>(sbuf);           // 4*32
        float (*s_scale)[16] = reinterpret_cast<float (*)[16]>(sbuf + 8 * 128); // 4*16

        if (tid < 4) {
            const int b = b0 + tid;
            float m[SPL], sm[SPL], gm = -3.4e38f;
            #pragma unroll
            for (int sp = 0; sp < SPL; sp++) {
                float2 stv = g_stats[b * SPL + sp];
                m[sp] = stv.x; sm[sp] = stv.y;
                gm = fmaxf(gm, stv.x);
            }
            float tot = 0.f;
            #pragma unroll
            for (int sp = 0; sp < SPL; sp++) tot += sm[sp] * expf(m[sp] - gm);
            const float inv = 1.f / tot;
            #pragma unroll
            for (int sp = 0; sp < SPL; sp++) s_scale[tid][sp] = expf(m[sp] - gm) * inv;
        }
        __syncthreads();

        for (int i = tid; i < 4 * 32; i += 256) {
            const int bb = i >> 5, j = i & 31;
            const int jj = ks * 32 + j;
            const int b = b0 + bb;
            float ms = 0.f;
            #pragma unroll
            for (int sp = 0; sp < SPL; sp++)
                ms += g_part[(size_t)(b * SPL + sp) * D_ + jj] * s_scale[bb][sp];
            s_msa[bb][j] = ms;
        }
        __syncthreads();
        float acc[4] = {};
        const float* Wb = W_s + (size_t)(ks * 32) * D_ + k;
        #pragma unroll 4
        for (int j = 0; j < 32; j++) {
            const float wv = __ldg(&Wb[(size_t)j * D_]);
            #pragma unroll
            for (int bb = 0; bb < 4; bb++) acc[bb] += s_msa[bb][j] * wv;
        }
        #pragma unroll
        for (int bb = 0; bb < 4; bb++)
            g_fsp[ks][(size_t)(b0 + bb) * D_ + k] = acc[bb];
        block_signal(&c_fs_bg[bg]);
        return;
    }

    // ================= epilogue (per batch; computes its own gate) =================
    {
        const int b = bid - BID_EPI;
        const int bg = b >> 3;
        const int warp = tid >> 5, lane = tid & 31;

        float* s_gate = sbuf;
        if (warp == 0) {
            float a = 0.f;
            #pragma unroll
            for (int j = 0; j < 16; j++)
                a += control[(size_t)b * D_ + lane + j * 32] * W_m3[lane + j * 32];
            #pragma unroll
            for (int o = 16; o; o >>= 1) a += __shfl_xor_sync(0xffffffffu, a, o);
            if (lane == 0) s_gate[0] = 1.f / (1.f + expf(-(a + b_m3[0])));
        }
        __syncthreads();

        block_wait(&c_f2_bg[bg], 16);
        block_wait(&c_fs_bg[bg], 64);

        const float g = s_gate[0];
        #pragma unroll
        for (int h = 0; h < 2; h++) {
            const int k = tid + h * 256;
            float acc = b_m2[k] + b_s[k];
            #pragma unroll
            for (int p = 0; p < F2_KS; p++) acc += g_f2p[p][(size_t)b * D_ + k];
            #pragma unroll
            for (int p = 0; p < FS_KS; p++) acc += g_fsp[p][(size_t)b * D_ + k];
            out[(size_t)b * D_ + k] = acc * g + (1.f - g) * memory[(size_t)b * D_ + k];
        }
        __threadfence();
        __syncthreads();
        if (tid == 0) {
            int old = atomicAdd(&c_epi, 1);
            if (old == B_ - 1) {
                c_m1 = 0;
                for (int q = 0; q < NBG; q++) { c_tile_bg[q] = 0; c_f2_bg[q] = 0; c_fs_bg[q] = 0; }
                c_epi = 0;
                __threadfence();
            }
        }
    }
}

// ---------------- launch ----------------
extern "C" void kernel_launch(void* const* d_in, const int* in_sizes, int n_in,
                              void* d_out, int out_size)
{
    const float* memory  = (const float*)d_in[0];
    const float* read    = (const float*)d_in[1];
    const float* control = (const float*)d_in[2];
    const float* past    = (const float*)d_in[3];
    const float* W_m1    = (const float*)d_in[4];
    const float* b_m1    = (const float*)d_in[5];
    const float* W_ca    = (const float*)d_in[6];
    const float* b_ca    = (const float*)d_in[7];
    const float* W_m2    = (const float*)d_in[8];
    const float* b_m2    = (const float*)d_in[9];
    const float* W_s     = (const float*)d_in[10];
    const float* b_s     = (const float*)d_in[11];
    const float* W_m3    = (const float*)d_in[12];
    const float* b_m3    = (const float*)d_in[13];
    float* out = (float*)d_out;

    kmain<<<GRID_TOTAL, 256>>>(past, control, W_ca, b_ca, memory, read,
                               W_m1, b_m1, W_m2, b_m2, W_s, b_s, W_m3, b_m3, out);
}

// round 15
// speedup vs baseline: 1.0125x; 1.0125x over previous
#include <cuda_runtime.h>
#include <math.h>

#define B_  128
#define T_  2048
#define D_  512
#define SPL 16                       // t-splits per batch
#define TS  (T_ / SPL)               // 128
#define NBG 16                       // batch groups of 8
#define NHG 32                       // half-groups of 4 batches
#define M1_KS 8                      // m1 GEMM split-K (K=1024, 128-wide)
#define F2_KS 8                      // m1@W_m2 split-K (K=512, 64-wide)
#define FS_KS 16                     // msa@W_s split-K (K=512, 32-wide)

// block-role layout: m1 | tiles | F2 | FS | epi
#define BID_M1     0                         // [0, 256)
#define BID_TILE   (BID_M1 + 256)            // [256, 2304)
#define BID_F2     (BID_TILE + B_ * SPL)     // [2304, 2560)
#define BID_FS     (BID_F2 + 256)            // [2560, 3584)  (1024 FS blocks)
#define BID_EPI    (BID_FS + 1024)           // [3584, 3712)
#define GRID_TOTAL (BID_EPI + B_)

// ---------------- scratch ----------------
__device__ float  g_part[B_ * SPL * D_];     // unnormalized msa partials (4 MB)
__device__ float2 g_stats[B_ * SPL];         // per-tile {local_max, local_expsum}
__device__ float  g_m1p[M1_KS][B_ * D_];     // m1 split-K partials
__device__ float  g_f2p[F2_KS][B_ * D_];     // m1@W_m2 partials
__device__ float  g_fsp[FS_KS][B_ * D_];     // msa@W_s partials

// pipeline counters (zero at load; reset by last epilogue block each run)
__device__ int c_m1;
__device__ int c_tile_hg[NHG];       // 64 tiles per half-group (4 batches)
__device__ int c_f2_bg[NBG];
__device__ int c_fs_bg[NBG];
__device__ int c_epi;

__device__ __forceinline__ void block_signal(int* c) {
    __threadfence();
    __syncthreads();
    if (threadIdx.x == 0) atomicAdd(c, 1);
}
__device__ __forceinline__ void block_wait(int* c, int target) {
    if (threadIdx.x == 0) {
        while (atomicAdd(c, 0) < target) __nanosleep(128);
        __threadfence();
    }
    __syncthreads();
}

__global__ __launch_bounds__(256, 5) void kmain(const float* __restrict__ past,
                                                const float* __restrict__ control,
                                                const float* __restrict__ W_ca,
                                                const float* __restrict__ b_ca,
                                                const float* __restrict__ memory,
                                                const float* __restrict__ read,
                                                const float* __restrict__ W_m1,
                                                const float* __restrict__ b_m1,
                                                const float* __restrict__ W_m2,
                                                const float* __restrict__ b_m2,
                                                const float* __restrict__ W_s,
                                                const float* __restrict__ b_s,
                                                const float* __restrict__ W_m3,
                                                const float* __restrict__ b_m3,
                                                float* __restrict__ out)
{
    __shared__ __align__(16) float sbuf[8 * 128 + 8 * 16];   // 4.5 KB, carved per role
    const int tid = threadIdx.x;
    const int bid = blockIdx.x;

    // ================= m1 GEMM (split-K 8, 128-wide) =================
    if (bid < BID_TILE) {
        const int idx = bid - BID_M1;
        const int ks = idx & 7, bg = (idx >> 3) & 15, st = idx >> 7;
        const int k = st * 256 + tid;
        float (*s_a)[128] = reinterpret_cast<float (*)[128]>(sbuf);
        for (int i = tid; i < 8 * 128; i += 256) {
            const int bb = i >> 7, j = i & 127;
            const int jj = ks * 128 + j;
            const int b = bg * 8 + bb;
            s_a[bb][j] = (jj < D_) ? memory[b * D_ + jj] : read[b * D_ + (jj - D_)];
        }
        __syncthreads();
        float acc[8] = {};
        const float* Wb = W_m1 + (size_t)(ks * 128) * D_ + k;
        #pragma unroll 4
        for (int j = 0; j < 128; j++) {
            const float wv = __ldg(&Wb[(size_t)j * D_]);
            #pragma unroll
            for (int bb = 0; bb < 8; bb++) acc[bb] += s_a[bb][j] * wv;
        }
        #pragma unroll
        for (int bb = 0; bb < 8; bb++)
            g_m1p[ks][(size_t)(bg * 8 + bb) * D_ + k] = acc[bb];
        block_signal(&c_m1);
        return;
    }

    // ================= fused logits+msa tile (the 1.07 GB stream) =================
    if (bid < BID_F2) {
        // carve: [0,512) c*W_ca (float4[128]); [512,640) logits; [640,768) weights; [768] red
        float4* s_cw    = reinterpret_cast<float4*>(sbuf);
        float*  s_logit = sbuf + 512;
        float*  s_w     = sbuf + 640;
        float*  s_red   = sbuf + 768;

        const int idx = bid - BID_TILE;
        const int b = idx >> 4, s = idx & 15;
        const int warp = tid >> 5, lane = tid & 31;
        const float* cbase = past + (size_t)b * T_ * (2 * D_) + (size_t)s * TS * (2 * D_);

        if (tid < D_ / 4) {
            float4 c = reinterpret_cast<const float4*>(control + (size_t)b * D_)[tid];
            float4 w = reinterpret_cast<const float4*>(W_ca)[tid];
            s_cw[tid] = make_float4(c.x * w.x, c.y * w.y, c.z * w.z, c.w * w.w);
        }
        __syncthreads();

        // --- phase A: 128 logits (8 warps x 16 t, two groups of 8 for MLP) ---
        const float bias = b_ca[0];
        #pragma unroll
        for (int g = 0; g < 2; g++) {
            const int t0 = warp * 16 + g * 8;
            float acc[8] = {};
            #pragma unroll
            for (int j = 0; j < 4; j++) {
                const float4 c = s_cw[lane + j * 32];
                #pragma unroll
                for (int i = 0; i < 8; i++) {
                    float4 v = __ldcs(reinterpret_cast<const float4*>(
                                   cbase + (size_t)(t0 + i) * (2 * D_)) + lane + j * 32);
                    acc[i] += v.x * c.x + v.y * c.y + v.z * c.z + v.w * c.w;
                }
            }
            #pragma unroll
            for (int i = 0; i < 8; i++) {
                float a = acc[i];
                #pragma unroll
                for (int o = 16; o; o >>= 1) a += __shfl_xor_sync(0xffffffffu, a, o);
                if (lane == 0) s_logit[t0 + i] = a + bias;
            }
        }
        __syncthreads();

        // --- local softmax stats (warp 0) ---
        if (warp == 0) {
            float v[4], m = -3.4e38f;
            #pragma unroll
            for (int q = 0; q < 4; q++) {
                float x = s_logit[lane + q * 32];
                if (x == 0.f) x = -1e9f;              // padding mask
                v[q] = x;
                m = fmaxf(m, x);
            }
            #pragma unroll
            for (int o = 16; o; o >>= 1) m = fmaxf(m, __shfl_xor_sync(0xffffffffu, m, o));
            float sum = 0.f;
            #pragma unroll
            for (int q = 0; q < 4; q++) sum += expf(v[q] - m);
            #pragma unroll
            for (int o = 16; o; o >>= 1) sum += __shfl_xor_sync(0xffffffffu, sum, o);
            if (lane == 0) { s_red[0] = m; g_stats[b * SPL + s] = make_float2(m, sum); }
        }
        __syncthreads();
        const float mx = s_red[0];
        if (tid < TS) {
            float x = s_logit[tid];
            if (x == 0.f) x = -1e9f;
            s_w[tid] = expf(x - mx);                  // unnormalized weight
        }
        __syncthreads();

        // --- phase B: weighted sum of memories half (float4; two row-parity halves) ---
        const float4* rbase = reinterpret_cast<const float4*>(cbase);   // row stride 256 float4
        const int c = tid & 127, half = tid >> 7;
        float4 a0 = {0,0,0,0}, a1 = {0,0,0,0};
        #pragma unroll 8
        for (int t = half; t < TS; t += 8) {
            float4 v0 = __ldcs(&rbase[(size_t)(t    ) * 256 + 128 + c]);
            float4 v1 = __ldcs(&rbase[(size_t)(t + 2) * 256 + 128 + c]);
            float4 v2 = __ldcs(&rbase[(size_t)(t + 4) * 256 + 128 + c]);
            float4 v3 = __ldcs(&rbase[(size_t)(t + 6) * 256 + 128 + c]);
            const float w0 = s_w[t], w1 = s_w[t + 2], w2 = s_w[t + 4], w3 = s_w[t + 6];
            a0.x += w0 * v0.x; a0.y += w0 * v0.y; a0.z += w0 * v0.z; a0.w += w0 * v0.w;
            a1.x += w1 * v1.x; a1.y += w1 * v1.y; a1.z += w1 * v1.z; a1.w += w1 * v1.w;
            a0.x += w2 * v2.x; a0.y += w2 * v2.y; a0.z += w2 * v2.z; a0.w += w2 * v2.w;
            a1.x += w3 * v3.x; a1.y += w3 * v3.y; a1.z += w3 * v3.z; a1.w += w3 * v3.w;
        }
        float4 acc = make_float4(a0.x + a1.x, a0.y + a1.y, a0.z + a1.z, a0.w + a1.w);

        // cross-half combine (reuse s_cw region; phase A no longer needs it)
        __syncthreads();
        if (half == 1) s_cw[c] = acc;
        __syncthreads();
        if (half == 0) {
            float4 o = s_cw[c];
            o.x += acc.x; o.y += acc.y; o.z += acc.z; o.w += acc.w;
            reinterpret_cast<float4*>(g_part + (size_t)(b * SPL + s) * D_)[c] = o;
        }
        block_signal(&c_tile_hg[b >> 2]);
        return;
    }

    // ================= m1@W_m2 GEMM (split-K 8, 64-wide); waits on m1 =================
    if (bid < BID_FS) {
        block_wait(&c_m1, 256);
        const int idx = bid - BID_F2;
        const int ks = idx & 7, bg = (idx >> 3) & 15, st = idx >> 7;
        const int k = st * 256 + tid;
        float (*s_m1)[64] = reinterpret_cast<float (*)[64]>(sbuf);
        for (int i = tid; i < 8 * 64; i += 256) {
            const int bb = i >> 6, j = i & 63;
            const int jj = ks * 64 + j;
            const int b = bg * 8 + bb;
            float m1 = b_m1[jj];
            #pragma unroll
            for (int p = 0; p < M1_KS; p++) m1 += g_m1p[p][(size_t)b * D_ + jj];
            s_m1[bb][j] = m1;
        }
        __syncthreads();
        float acc[8] = {};
        const float* Wb = W_m2 + (size_t)(ks * 64) * D_ + k;
        #pragma unroll 4
        for (int j = 0; j < 64; j++) {
            const float wv = __ldg(&Wb[(size_t)j * D_]);
            #pragma unroll
            for (int bb = 0; bb < 8; bb++) acc[bb] += s_m1[bb][j] * wv;
        }
        #pragma unroll
        for (int bb = 0; bb < 8; bb++)
            g_f2p[ks][(size_t)(bg * 8 + bb) * D_ + k] = acc[bb];
        block_signal(&c_f2_bg[bg]);
        return;
    }

    // ================= msa@W_s GEMM (split-K 16, 32-wide, 4 batches/block) =================
    if (bid < BID_EPI) {
        const int idx = bid - BID_FS;            // [0, 1024)
        const int ks = idx & 15;                 // 16 k-slices (32-wide)
        const int bh = (idx >> 4) & 1;           // batch half within bg (4 batches)
        const int bg = (idx >> 5) & 15;
        const int st = idx >> 9;                 // 2 column tiles of 256
        block_wait(&c_tile_hg[bg * 2 + bh], 4 * SPL);   // only this block's 4 batches
        const int k = st * 256 + tid;
        const int b0 = bg * 8 + bh * 4;

        float (*s_msa)[32]   = reinterpret_cast<float (*)[32]>(sbuf);           // 4*32
        float (*s_scale)[16] = reinterpret_cast<float (*)[16]>(sbuf + 8 * 128); // 4*16

        if (tid < 4) {
            const int b = b0 + tid;
            float m[SPL], sm[SPL], gm = -3.4e38f;
            #pragma unroll
            for (int sp = 0; sp < SPL; sp++) {
                float2 stv = g_stats[b * SPL + sp];
                m[sp] = stv.x; sm[sp] = stv.y;
                gm = fmaxf(gm, stv.x);
            }
            float tot = 0.f;
            #pragma unroll
            for (int sp = 0; sp < SPL; sp++) tot += sm[sp] * expf(m[sp] - gm);
            const float inv = 1.f / tot;
            #pragma unroll
            for (int sp = 0; sp < SPL; sp++) s_scale[tid][sp] = expf(m[sp] - gm) * inv;
        }
        __syncthreads();

        for (int i = tid; i < 4 * 32; i += 256) {
            const int bb = i >> 5, j = i & 31;
            const int jj = ks * 32 + j;
            const int b = b0 + bb;
            float ms = 0.f;
            #pragma unroll
            for (int sp = 0; sp < SPL; sp++)
                ms += g_part[(size_t)(b * SPL + sp) * D_ + jj] * s_scale[bb][sp];
            s_msa[bb][j] = ms;
        }
        __syncthreads();
        float acc[4] = {};
        const float* Wb = W_s + (size_t)(ks * 32) * D_ + k;
        #pragma unroll 4
        for (int j = 0; j < 32; j++) {
            const float wv = __ldg(&Wb[(size_t)j * D_]);
            #pragma unroll
            for (int bb = 0; bb < 4; bb++) acc[bb] += s_msa[bb][j] * wv;
        }
        #pragma unroll
        for (int bb = 0; bb < 4; bb++)
            g_fsp[ks][(size_t)(b0 + bb) * D_ + k] = acc[bb];
        block_signal(&c_fs_bg[bg]);
        return;
    }

    // ================= epilogue (per batch; computes its own gate) =================
    {
        const int b = bid - BID_EPI;
        const int bg = b >> 3;
        const int warp = tid >> 5, lane = tid & 31;

        float* s_gate = sbuf;
        if (warp == 0) {
            float a = 0.f;
            #pragma unroll
            for (int j = 0; j < 16; j++)
                a += control[(size_t)b * D_ + lane + j * 32] * W_m3[lane + j * 32];
            #pragma unroll
            for (int o = 16; o; o >>= 1) a += __shfl_xor_sync(0xffffffffu, a, o);
            if (lane == 0) s_gate[0] = 1.f / (1.f + expf(-(a + b_m3[0])));
        }
        __syncthreads();

        block_wait(&c_f2_bg[bg], 16);
        block_wait(&c_fs_bg[bg], 64);

        const float g = s_gate[0];
        #pragma unroll
        for (int h = 0; h < 2; h++) {
            const int k = tid + h * 256;
            float acc = b_m2[k] + b_s[k];
            #pragma unroll
            for (int p = 0; p < F2_KS; p++) acc += g_f2p[p][(size_t)b * D_ + k];
            #pragma unroll
            for (int p = 0; p < FS_KS; p++) acc += g_fsp[p][(size_t)b * D_ + k];
            out[(size_t)b * D_ + k] = acc * g + (1.f - g) * memory[(size_t)b * D_ + k];
        }
        __threadfence();
        __syncthreads();
        if (tid == 0) {
            int old = atomicAdd(&c_epi, 1);
            if (old == B_ - 1) {
                c_m1 = 0;
                for (int q = 0; q < NHG; q++) c_tile_hg[q] = 0;
                for (int q = 0; q < NBG; q++) { c_f2_bg[q] = 0; c_fs_bg[q] = 0; }
                c_epi = 0;
                __threadfence();
            }
        }
    }
}

// ---------------- launch ----------------
extern "C" void kernel_launch(void* const* d_in, const int* in_sizes, int n_in,
                              void* d_out, int out_size)
{
    const float* memory  = (const float*)d_in[0];
    const float* read    = (const float*)d_in[1];
    const float* control = (const float*)d_in[2];
    const float* past    = (const float*)d_in[3];
    const float* W_m1    = (const float*)d_in[4];
    const float* b_m1    = (const float*)d_in[5];
    const float* W_ca    = (const float*)d_in[6];
    const float* b_ca    = (const float*)d_in[7];
    const float* W_m2    = (const float*)d_in[8];
    const float* b_m2    = (const float*)d_in[9];
    const float* W_s     = (const float*)d_in[10];
    const float* b_s     = (const float*)d_in[11];
    const float* W_m3    = (const float*)d_in[12];
    const float* b_m3    = (const float*)d_in[13];
    float* out = (float*)d_out;

    kmain<<<GRID_TOTAL, 256>>>(past, control, W_ca, b_ca, memory, read,
                               W_m1, b_m1, W_m2, b_m2, W_s, b_s, W_m3, b_m3, out);
}

// round 16
// speedup vs baseline: 1.0368x; 1.0240x over previous
#include <cuda_runtime.h>
#include <math.h>

#define B_  128
#define T_  2048
#define D_  512
#define SPL 16                       // t-splits per batch
#define TS  (T_ / SPL)               // 128
#define NBG 16                       // batch groups of 8
#define M1_KS 8                      // m1 GEMM split-K (K=1024, 128-wide)
#define F2_KS 8                      // m1@W_m2 split-K (K=512, 64-wide)
#define FS_KS 16                     // msa@W_s split-K (K=512, 32-wide)

// block-role layout: m1 (128 fat blocks) | tiles | F2 | FS | epi
#define BID_M1     0                         // [0, 128)
#define BID_TILE   (BID_M1 + 128)            // [128, 2176)
#define BID_F2     (BID_TILE + B_ * SPL)     // [2176, 2432)
#define BID_FS     (BID_F2 + 256)            // [2432, 3456)  (1024 FS blocks)
#define BID_EPI    (BID_FS + 1024)           // [3456, 3584)
#define GRID_TOTAL (BID_EPI + B_)

// ---------------- scratch ----------------
__device__ float  g_part[B_ * SPL * D_];     // unnormalized msa partials (4 MB)
__device__ float2 g_stats[B_ * SPL];         // per-tile {local_max, local_expsum}
__device__ float  g_m1p[M1_KS][B_ * D_];     // m1 split-K partials
__device__ float  g_f2p[F2_KS][B_ * D_];     // m1@W_m2 partials
__device__ float  g_fsp[FS_KS][B_ * D_];     // msa@W_s partials

// pipeline counters (zero at load; reset by last epilogue block each run)
__device__ int c_m1;
__device__ int c_tile_bg[NBG];
__device__ int c_f2_bg[NBG];
__device__ int c_fs_bg[NBG];
__device__ int c_epi;

__device__ __forceinline__ void block_signal(int* c) {
    __threadfence();
    __syncthreads();
    if (threadIdx.x == 0) atomicAdd(c, 1);
}
__device__ __forceinline__ void block_wait(int* c, int target) {
    if (threadIdx.x == 0) {
        while (atomicAdd(c, 0) < target) __nanosleep(128);
        __threadfence();
    }
    __syncthreads();
}

__global__ __launch_bounds__(256, 5) void kmain(const float* __restrict__ past,
                                                const float* __restrict__ control,
                                                const float* __restrict__ W_ca,
                                                const float* __restrict__ b_ca,
                                                const float* __restrict__ memory,
                                                const float* __restrict__ read,
                                                const float* __restrict__ W_m1,
                                                const float* __restrict__ b_m1,
                                                const float* __restrict__ W_m2,
                                                const float* __restrict__ b_m2,
                                                const float* __restrict__ W_s,
                                                const float* __restrict__ b_s,
                                                const float* __restrict__ W_m3,
                                                const float* __restrict__ b_m3,
                                                float* __restrict__ out)
{
    __shared__ __align__(16) float sbuf[8 * 128 + 8 * 16];   // 4.5 KB, carved per role
    const int tid = threadIdx.x;
    const int bid = blockIdx.x;

    // ================= m1 GEMM (split-K 8, 128-wide; 2 column strips/block) =================
    if (bid < BID_TILE) {
        const int idx = bid - BID_M1;
        const int ks = idx & 7, bg = idx >> 3;        // 128 blocks: (ks, bg)
        float (*s_a)[128] = reinterpret_cast<float (*)[128]>(sbuf);
        for (int i = tid; i < 8 * 128; i += 256) {
            const int bb = i >> 7, j = i & 127;
            const int jj = ks * 128 + j;
            const int b = bg * 8 + bb;
            s_a[bb][j] = (jj < D_) ? memory[b * D_ + jj] : read[b * D_ + (jj - D_)];
        }
        __syncthreads();
        #pragma unroll
        for (int st = 0; st < 2; st++) {
            const int k = st * 256 + tid;
            float acc[8] = {};
            const float* Wb = W_m1 + (size_t)(ks * 128) * D_ + k;
            #pragma unroll 4
            for (int j = 0; j < 128; j++) {
                const float wv = __ldg(&Wb[(size_t)j * D_]);
                #pragma unroll
                for (int bb = 0; bb < 8; bb++) acc[bb] += s_a[bb][j] * wv;
            }
            #pragma unroll
            for (int bb = 0; bb < 8; bb++)
                g_m1p[ks][(size_t)(bg * 8 + bb) * D_ + k] = acc[bb];
        }
        block_signal(&c_m1);
        return;
    }

    // ================= fused logits+msa tile (the 1.07 GB stream) =================
    if (bid < BID_F2) {
        // carve: [0,512) c*W_ca (float4[128]); [512,640) logits; [640,768) weights; [768] red
        float4* s_cw    = reinterpret_cast<float4*>(sbuf);
        float*  s_logit = sbuf + 512;
        float*  s_w     = sbuf + 640;
        float*  s_red   = sbuf + 768;

        const int idx = bid - BID_TILE;
        const int b = idx >> 4, s = idx & 15;
        const int warp = tid >> 5, lane = tid & 31;
        const float* cbase = past + (size_t)b * T_ * (2 * D_) + (size_t)s * TS * (2 * D_);

        if (tid < D_ / 4) {
            float4 c = reinterpret_cast<const float4*>(control + (size_t)b * D_)[tid];
            float4 w = reinterpret_cast<const float4*>(W_ca)[tid];
            s_cw[tid] = make_float4(c.x * w.x, c.y * w.y, c.z * w.z, c.w * w.w);
        }
        __syncthreads();

        // --- phase A: 128 logits (8 warps x 16 t, two groups of 8 for MLP) ---
        const float bias = b_ca[0];
        #pragma unroll
        for (int g = 0; g < 2; g++) {
            const int t0 = warp * 16 + g * 8;
            float acc[8] = {};
            #pragma unroll
            for (int j = 0; j < 4; j++) {
                const float4 c = s_cw[lane + j * 32];
                #pragma unroll
                for (int i = 0; i < 8; i++) {
                    float4 v = __ldcs(reinterpret_cast<const float4*>(
                                   cbase + (size_t)(t0 + i) * (2 * D_)) + lane + j * 32);
                    acc[i] += v.x * c.x + v.y * c.y + v.z * c.z + v.w * c.w;
                }
            }
            #pragma unroll
            for (int i = 0; i < 8; i++) {
                float a = acc[i];
                #pragma unroll
                for (int o = 16; o; o >>= 1) a += __shfl_xor_sync(0xffffffffu, a, o);
                if (lane == 0) s_logit[t0 + i] = a + bias;
            }
        }
        __syncthreads();

        // --- local softmax stats (warp 0) ---
        if (warp == 0) {
            float v[4], m = -3.4e38f;
            #pragma unroll
            for (int q = 0; q < 4; q++) {
                float x = s_logit[lane + q * 32];
                if (x == 0.f) x = -1e9f;              // padding mask
                v[q] = x;
                m = fmaxf(m, x);
            }
            #pragma unroll
            for (int o = 16; o; o >>= 1) m = fmaxf(m, __shfl_xor_sync(0xffffffffu, m, o));
            float sum = 0.f;
            #pragma unroll
            for (int q = 0; q < 4; q++) sum += expf(v[q] - m);
            #pragma unroll
            for (int o = 16; o; o >>= 1) sum += __shfl_xor_sync(0xffffffffu, sum, o);
            if (lane == 0) { s_red[0] = m; g_stats[b * SPL + s] = make_float2(m, sum); }
        }
        __syncthreads();
        const float mx = s_red[0];
        if (tid < TS) {
            float x = s_logit[tid];
            if (x == 0.f) x = -1e9f;
            s_w[tid] = expf(x - mx);                  // unnormalized weight
        }
        __syncthreads();

        // --- phase B: weighted sum of memories half (float4; two row-parity halves) ---
        const float4* rbase = reinterpret_cast<const float4*>(cbase);   // row stride 256 float4
        const int c = tid & 127, half = tid >> 7;
        float4 a0 = {0,0,0,0}, a1 = {0,0,0,0};
        #pragma unroll 8
        for (int t = half; t < TS; t += 8) {
            float4 v0 = __ldcs(&rbase[(size_t)(t    ) * 256 + 128 + c]);
            float4 v1 = __ldcs(&rbase[(size_t)(t + 2) * 256 + 128 + c]);
            float4 v2 = __ldcs(&rbase[(size_t)(t + 4) * 256 + 128 + c]);
            float4 v3 = __ldcs(&rbase[(size_t)(t + 6) * 256 + 128 + c]);
            const float w0 = s_w[t], w1 = s_w[t + 2], w2 = s_w[t + 4], w3 = s_w[t + 6];
            a0.x += w0 * v0.x; a0.y += w0 * v0.y; a0.z += w0 * v0.z; a0.w += w0 * v0.w;
            a1.x += w1 * v1.x; a1.y += w1 * v1.y; a1.z += w1 * v1.z; a1.w += w1 * v1.w;
            a0.x += w2 * v2.x; a0.y += w2 * v2.y; a0.z += w2 * v2.z; a0.w += w2 * v2.w;
            a1.x += w3 * v3.x; a1.y += w3 * v3.y; a1.z += w3 * v3.z; a1.w += w3 * v3.w;
        }
        float4 acc = make_float4(a0.x + a1.x, a0.y + a1.y, a0.z + a1.z, a0.w + a1.w);

        // cross-half combine (reuse s_cw region; phase A no longer needs it)
        __syncthreads();
        if (half == 1) s_cw[c] = acc;
        __syncthreads();
        if (half == 0) {
            float4 o = s_cw[c];
            o.x += acc.x; o.y += acc.y; o.z += acc.z; o.w += acc.w;
            reinterpret_cast<float4*>(g_part + (size_t)(b * SPL + s) * D_)[c] = o;
        }
        block_signal(&c_tile_bg[b >> 3]);
        return;
    }

    // ================= m1@W_m2 GEMM (split-K 8, 64-wide); waits on m1 =================
    if (bid < BID_FS) {
        block_wait(&c_m1, 128);
        const int idx = bid - BID_F2;
        const int ks = idx & 7, bg = (idx >> 3) & 15, st = idx >> 7;
        const int k = st * 256 + tid;
        float (*s_m1)[64] = reinterpret_cast<float (*)[64]>(sbuf);
        for (int i = tid; i < 8 * 64; i += 256) {
            const int bb = i >> 6, j = i & 63;
            const int jj = ks * 64 + j;
            const int b = bg * 8 + bb;
            float m1 = b_m1[jj];
            #pragma unroll
            for (int p = 0; p < M1_KS; p++) m1 += g_m1p[p][(size_t)b * D_ + jj];
            s_m1[bb][j] = m1;
        }
        __syncthreads();
        float acc[8] = {};
        const float* Wb = W_m2 + (size_t)(ks * 64) * D_ + k;
        #pragma unroll 4
        for (int j = 0; j < 64; j++) {
            const float wv = __ldg(&Wb[(size_t)j * D_]);
            #pragma unroll
            for (int bb = 0; bb < 8; bb++) acc[bb] += s_m1[bb][j] * wv;
        }
        #pragma unroll
        for (int bb = 0; bb < 8; bb++)
            g_f2p[ks][(size_t)(bg * 8 + bb) * D_ + k] = acc[bb];
        block_signal(&c_f2_bg[bg]);
        return;
    }

    // ================= msa@W_s GEMM (split-K 16, 32-wide, 4 batches/block) =================
    if (bid < BID_EPI) {
        const int idx = bid - BID_FS;            // [0, 1024)
        const int ks = idx & 15;                 // 16 k-slices (32-wide)
        const int bh = (idx >> 4) & 1;           // batch half within bg (4 batches)
        const int bg = (idx >> 5) & 15;
        const int st = idx >> 9;                 // 2 column tiles of 256
        block_wait(&c_tile_bg[bg], 8 * SPL);
        const int k = st * 256 + tid;
        const int b0 = bg * 8 + bh * 4;

        float (*s_msa)[32]   = reinterpret_cast<float (*)[32]>(sbuf);           // 4*32
        float (*s_scale)[16] = reinterpret_cast<float (*)[16]>(sbuf + 8 * 128); // 4*16

        if (tid < 4) {
            const int b = b0 + tid;
            float m[SPL], sm[SPL], gm = -3.4e38f;
            #pragma unroll
            for (int sp = 0; sp < SPL; sp++) {
                float2 stv = g_stats[b * SPL + sp];
                m[sp] = stv.x; sm[sp] = stv.y;
                gm = fmaxf(gm, stv.x);
            }
            float tot = 0.f;
            #pragma unroll
            for (int sp = 0; sp < SPL; sp++) tot += sm[sp] * expf(m[sp] - gm);
            const float inv = 1.f / tot;
            #pragma unroll
            for (int sp = 0; sp < SPL; sp++) s_scale[tid][sp] = expf(m[sp] - gm) * inv;
        }
        __syncthreads();

        for (int i = tid; i < 4 * 32; i += 256) {
            const int bb = i >> 5, j = i & 31;
            const int jj = ks * 32 + j;
            const int b = b0 + bb;
            float ms = 0.f;
            #pragma unroll
            for (int sp = 0; sp < SPL; sp++)
                ms += g_part[(size_t)(b * SPL + sp) * D_ + jj] * s_scale[bb][sp];
            s_msa[bb][j] = ms;
        }
        __syncthreads();
        float acc[4] = {};
        const float* Wb = W_s + (size_t)(ks * 32) * D_ + k;
        #pragma unroll 4
        for (int j = 0; j < 32; j++) {
            const float wv = __ldg(&Wb[(size_t)j * D_]);
            #pragma unroll
            for (int bb = 0; bb < 4; bb++) acc[bb] += s_msa[bb][j] * wv;
        }
        #pragma unroll
        for (int bb = 0; bb < 4; bb++)
            g_fsp[ks][(size_t)(b0 + bb) * D_ + k] = acc[bb];
        block_signal(&c_fs_bg[bg]);
        return;
    }

    // ================= epilogue (per batch; computes its own gate) =================
    {
        const int b = bid - BID_EPI;
        const int bg = b >> 3;
        const int warp = tid >> 5, lane = tid & 31;

        float* s_gate = sbuf;
        if (warp == 0) {
            float a = 0.f;
            #pragma unroll
            for (int j = 0; j < 16; j++)
                a += control[(size_t)b * D_ + lane + j * 32] * W_m3[lane + j * 32];
            #pragma unroll
            for (int o = 16; o; o >>= 1) a += __shfl_xor_sync(0xffffffffu, a, o);
            if (lane == 0) s_gate[0] = 1.f / (1.f + expf(-(a + b_m3[0])));
        }
        __syncthreads();

        block_wait(&c_f2_bg[bg], 16);
        block_wait(&c_fs_bg[bg], 64);

        const float g = s_gate[0];
        #pragma unroll
        for (int h = 0; h < 2; h++) {
            const int k = tid + h * 256;
            float acc = b_m2[k] + b_s[k];
            #pragma unroll
            for (int p = 0; p < F2_KS; p++) acc += g_f2p[p][(size_t)b * D_ + k];
            #pragma unroll
            for (int p = 0; p < FS_KS; p++) acc += g_fsp[p][(size_t)b * D_ + k];
            out[(size_t)b * D_ + k] = acc * g + (1.f - g) * memory[(size_t)b * D_ + k];
        }
        __threadfence();
        __syncthreads();
        if (tid == 0) {
            int old = atomicAdd(&c_epi, 1);
            if (old == B_ - 1) {
                c_m1 = 0;
                for (int q = 0; q < NBG; q++) { c_tile_bg[q] = 0; c_f2_bg[q] = 0; c_fs_bg[q] = 0; }
                c_epi = 0;
                __threadfence();
            }
        }
    }
}

// ---------------- launch ----------------
extern "C" void kernel_launch(void* const* d_in, const int* in_sizes, int n_in,
                              void* d_out, int out_size)
{
    const float* memory  = (const float*)d_in[0];
    const float* read    = (const float*)d_in[1];
    const float* control = (const float*)d_in[2];
    const float* past    = (const float*)d_in[3];
    const float* W_m1    = (const float*)d_in[4];
    const float* b_m1    = (const float*)d_in[5];
    const float* W_ca    = (const float*)d_in[6];
    const float* b_ca    = (const float*)d_in[7];
    const float* W_m2    = (const float*)d_in[8];
    const float* b_m2    = (const float*)d_in[9];
    const float* W_s     = (const float*)d_in[10];
    const float* b_s     = (const float*)d_in[11];
    const float* W_m3    = (const float*)d_in[12];
    const float* b_m3    = (const float*)d_in[13];
    float* out = (float*)d_out;

    kmain<<<GRID_TOTAL, 256>>>(past, control, W_ca, b_ca, memory, read,
                               W_m1, b_m1, W_m2, b_m2, W_s, b_s, W_m3, b_m3, out);
}